// round 2
// baseline (speedup 1.0000x reference)
#include <cuda_runtime.h>

#define NQ 8192          // rows per side (users == items == 8192)
#define D 32             // q/k dim
#define DV 64            // V' dim (after folding W)
#define KNB 4            // neighbors
#define IN_DIM 256       // K*(D+D)

#define BM 64
#define BN 64
#define PAD 4
#define SK (BN + PAD)    // 68, row stride of transposed K tile
#define SQ (BM + PAD)    // 68
#define SV (DV + PAD)    // 68
#define SP (BM + PAD)    // 68

// Scratch: V' = cat @ W per side (2 x 2 MB)
__device__ float g_Vu[NQ * DV];
__device__ float g_Vi[NQ * DV];

// ---------------------------------------------------------------------------
// Phase 1: V'[u, :] = concat_k(vecA[idxA[u,k]], vecB[idxB[u,k]]) @ W
// Block: 128 threads, 8 users. Each thread: 1 user x 4 output cols (float4).
// ---------------------------------------------------------------------------
__global__ __launch_bounds__(128) void build_v_kernel(
    const float* __restrict__ vecA,   // review_vecs [*, 32]
    const int*   __restrict__ idxA,   // [NQ, 4]
    const float* __restrict__ vecB,   // item or user vecs [*, 32]
    const int*   __restrict__ idxB,   // [NQ, 4]
    const float* __restrict__ W,      // [256, 64]
    int side)                          // 0 -> g_Vu, 1 -> g_Vi
{
    __shared__ float cat_s[8][IN_DIM];
    const int tid = threadIdx.x;
    const int u0 = blockIdx.x * 8;

    // Gather 8 users x 256 features into smem
    for (int t = tid; t < 8 * IN_DIM; t += 128) {
        const int lu  = t >> 8;
        const int pos = t & 255;
        const int k   = pos >> 6;
        const int w   = pos & 63;
        const int gu  = u0 + lu;
        float v;
        if (w < 32) v = vecA[idxA[gu * KNB + k] * D + w];
        else        v = vecB[idxB[gu * KNB + k] * D + (w - 32)];
        cat_s[lu][pos] = v;
    }
    __syncthreads();

    const int lu = tid >> 4;    // 0..7
    const int og = tid & 15;    // 0..15 -> 4 output cols each
    const float4* W4 = reinterpret_cast<const float4*>(W);
    float4 acc = make_float4(0.f, 0.f, 0.f, 0.f);
#pragma unroll 8
    for (int i = 0; i < IN_DIM; i++) {
        const float c  = cat_s[lu][i];
        const float4 w4 = W4[i * 16 + og];
        acc.x += c * w4.x; acc.y += c * w4.y;
        acc.z += c * w4.z; acc.w += c * w4.w;
    }
    float* out = side ? g_Vi : g_Vu;
    reinterpret_cast<float4*>(out)[(u0 + lu) * 16 + og] = acc;
}

// ---------------------------------------------------------------------------
// Phase 2: fused flash attention (fp32), O = softmax(Q Q^T / sqrt(D) + 1) @ V'
// followed by ReLU.  Block: 256 threads = 16x16, each thread 4x4 S-subtile
// and 4x4 O-subtile.  BM=BN=64.  K tile and V tile share one smem buffer.
// ---------------------------------------------------------------------------
__global__ __launch_bounds__(256) void flash_kernel(
    const float* __restrict__ user_vecs,
    const float* __restrict__ item_vecs,
    float* __restrict__ out)
{
    __shared__ float Qt[D * SQ];           // transposed: Qt[dd][row]
    __shared__ float KVu[BN * SV];         // union: Kt[D][SK] / Vt[BN][SV]
    __shared__ float Pt[BN * SP];          // transposed P: Pt[col][row]

    const int side = blockIdx.y;
    const float* __restrict__ Q = side ? item_vecs : user_vecs;
    const float* __restrict__ V = side ? g_Vi : g_Vu;
    float* __restrict__ O = out + side * (NQ * DV);

    const int tid = threadIdx.x;
    const int ty = tid >> 4;    // 0..15 -> rows ty*4..+3
    const int tx = tid & 15;    // 0..15 -> cols tx*4..+3
    const int bm0 = blockIdx.x * BM;

    // Load Q tile transposed (once)
    for (int t = tid; t < BM * D; t += 256) {
        const int row = t >> 5, dd = t & 31;
        Qt[dd * SQ + row] = Q[(bm0 + row) * D + dd];
    }

    float m[4], l[4], acc[4][4];
#pragma unroll
    for (int r = 0; r < 4; r++) {
        m[r] = -1e30f; l[r] = 0.f;
#pragma unroll
        for (int c = 0; c < 4; c++) acc[r][c] = 0.f;
    }

    const float scale = 0.17677669529663687f;   // 1/sqrt(32)

    for (int j0 = 0; j0 < NQ; j0 += BN) {
        __syncthreads();   // previous Vt reads done (also orders Qt load, iter 0)
        // --- load K tile transposed into union buffer ---
        for (int t = tid; t < BN * D; t += 256) {
            const int row = t >> 5, dd = t & 31;
            KVu[dd * SK + row] = Q[(j0 + row) * D + dd];
        }
        __syncthreads();

        // --- S = Q K^T ---
        float s[4][4];
#pragma unroll
        for (int r = 0; r < 4; r++)
#pragma unroll
            for (int c = 0; c < 4; c++) s[r][c] = 0.f;

#pragma unroll 8
        for (int dd = 0; dd < D; dd++) {
            const float4 q4 = *reinterpret_cast<const float4*>(&Qt[dd * SQ + ty * 4]);
            const float4 k4 = *reinterpret_cast<const float4*>(&KVu[dd * SK + tx * 4]);
            s[0][0] += q4.x * k4.x; s[0][1] += q4.x * k4.y; s[0][2] += q4.x * k4.z; s[0][3] += q4.x * k4.w;
            s[1][0] += q4.y * k4.x; s[1][1] += q4.y * k4.y; s[1][2] += q4.y * k4.z; s[1][3] += q4.y * k4.w;
            s[2][0] += q4.z * k4.x; s[2][1] += q4.z * k4.y; s[2][2] += q4.z * k4.z; s[2][3] += q4.z * k4.w;
            s[3][0] += q4.w * k4.x; s[3][1] += q4.w * k4.y; s[3][2] += q4.w * k4.z; s[3][3] += q4.w * k4.w;
        }

        // --- online softmax update (row state replicated across 16 tx lanes) ---
        float p[4][4], corr[4];
#pragma unroll
        for (int r = 0; r < 4; r++) {
            float tmax = -1e30f;
#pragma unroll
            for (int c = 0; c < 4; c++) {
                s[r][c] = s[r][c] * scale + 1.0f;
                tmax = fmaxf(tmax, s[r][c]);
            }
#pragma unroll
            for (int o = 8; o >= 1; o >>= 1)
                tmax = fmaxf(tmax, __shfl_xor_sync(0xffffffffu, tmax, o));
            const float mn = fmaxf(m[r], tmax);
            corr[r] = __expf(m[r] - mn);
            float tsum = 0.f;
#pragma unroll
            for (int c = 0; c < 4; c++) {
                p[r][c] = __expf(s[r][c] - mn);
                tsum += p[r][c];
            }
#pragma unroll
            for (int o = 8; o >= 1; o >>= 1)
                tsum += __shfl_xor_sync(0xffffffffu, tsum, o);
            l[r] = l[r] * corr[r] + tsum;
            m[r] = mn;
        }

        // --- write P transposed: Pt[col][row] ---
#pragma unroll
        for (int cc = 0; cc < 4; cc++) {
            const float4 pv = make_float4(p[0][cc], p[1][cc], p[2][cc], p[3][cc]);
            *reinterpret_cast<float4*>(&Pt[(tx * 4 + cc) * SP + ty * 4]) = pv;
        }
        __syncthreads();   // Pt complete; Kt no longer needed

        // --- load V tile into union buffer (overwrites K tile) ---
        for (int t = tid * 4; t < BN * DV; t += 1024) {
            const int row = t >> 6, col = t & 63;
            *reinterpret_cast<float4*>(&KVu[row * SV + col]) =
                *reinterpret_cast<const float4*>(&V[(j0 + row) * DV + col]);
        }
        __syncthreads();

        // --- rescale O, accumulate P @ V ---
#pragma unroll
        for (int r = 0; r < 4; r++) {
            const float cr = corr[r];
#pragma unroll
            for (int c = 0; c < 4; c++) acc[r][c] *= cr;
        }
#pragma unroll 4
        for (int j = 0; j < BN; j++) {
            const float4 p4 = *reinterpret_cast<const float4*>(&Pt[j * SP + ty * 4]);
            const float4 v4 = *reinterpret_cast<const float4*>(&KVu[j * SV + tx * 4]);
            acc[0][0] += p4.x * v4.x; acc[0][1] += p4.x * v4.y; acc[0][2] += p4.x * v4.z; acc[0][3] += p4.x * v4.w;
            acc[1][0] += p4.y * v4.x; acc[1][1] += p4.y * v4.y; acc[1][2] += p4.y * v4.z; acc[1][3] += p4.y * v4.w;
            acc[2][0] += p4.z * v4.x; acc[2][1] += p4.z * v4.y; acc[2][2] += p4.z * v4.z; acc[2][3] += p4.z * v4.w;
            acc[3][0] += p4.w * v4.x; acc[3][1] += p4.w * v4.y; acc[3][2] += p4.w * v4.z; acc[3][3] += p4.w * v4.w;
        }
    }

    // --- epilogue: normalize, ReLU, store ---
#pragma unroll
    for (int r = 0; r < 4; r++) {
        const float inv = 1.f / l[r];
        const int row = bm0 + ty * 4 + r;
        const float4 o4 = make_float4(
            fmaxf(acc[r][0] * inv, 0.f),
            fmaxf(acc[r][1] * inv, 0.f),
            fmaxf(acc[r][2] * inv, 0.f),
            fmaxf(acc[r][3] * inv, 0.f));
        *reinterpret_cast<float4*>(&O[row * DV + tx * 4]) = o4;
    }
}

// ---------------------------------------------------------------------------
// Launch
// ---------------------------------------------------------------------------
extern "C" void kernel_launch(void* const* d_in, const int* in_sizes, int n_in,
                              void* d_out, int out_size)
{
    (void)in_sizes; (void)n_in; (void)out_size;
    const float* review = (const float*)d_in[0];
    const float* user   = (const float*)d_in[1];
    const float* item   = (const float*)d_in[2];
    const int*   adj_ur = (const int*)d_in[3];
    const int*   adj_ri = (const int*)d_in[4];
    const int*   adj_ir = (const int*)d_in[5];
    const int*   adj_ru = (const int*)d_in[6];
    const float* Wu     = (const float*)d_in[7];
    const float* Wi     = (const float*)d_in[8];
    float* out = (float*)d_out;

    // Phase 1: fold gather+concat+W into V' per side
    build_v_kernel<<<NQ / 8, 128>>>(review, adj_ur, item, adj_ri, Wu, 0);
    build_v_kernel<<<NQ / 8, 128>>>(review, adj_ir, user, adj_ru, Wi, 1);

    // Phase 2: fused attention for both sides
    dim3 grid(NQ / BM, 2);
    flash_kernel<<<grid, 256>>>(user, item, out);
}

// round 3
// speedup vs baseline: 1.0000x; 1.0000x over previous
#include <cuda_runtime.h>

#define NQ 8192          // rows per side (users == items == 8192)
#define D 32             // q/k dim
#define DV 64            // V' dim (after folding W)
#define KNB 4            // neighbors
#define IN_DIM 256       // K*(D+D)

#define BM 64
#define BN 64
#define PAD 4
#define SK (BN + PAD)    // 68, row stride of transposed K tile
#define SQ (BM + PAD)    // 68
#define SV (DV + PAD)    // 68
#define SP (BM + PAD)    // 68

// Scratch: V' = cat @ W per side (2 x 2 MB)
__device__ float g_Vu[NQ * DV];
__device__ float g_Vi[NQ * DV];

// ---------------------------------------------------------------------------
// Phase 1: V'[u, :] = concat_k(vecA[idxA[u,k]], vecB[idxB[u,k]]) @ W
// Block: 128 threads, 8 users. Each thread: 1 user x 4 output cols (float4).
// ---------------------------------------------------------------------------
__global__ __launch_bounds__(128) void build_v_kernel(
    const float* __restrict__ vecA,   // review_vecs [*, 32]
    const int*   __restrict__ idxA,   // [NQ, 4]
    const float* __restrict__ vecB,   // item or user vecs [*, 32]
    const int*   __restrict__ idxB,   // [NQ, 4]
    const float* __restrict__ W,      // [256, 64]
    int side)                          // 0 -> g_Vu, 1 -> g_Vi
{
    __shared__ float cat_s[8][IN_DIM];
    const int tid = threadIdx.x;
    const int u0 = blockIdx.x * 8;

    // Gather 8 users x 256 features into smem
    for (int t = tid; t < 8 * IN_DIM; t += 128) {
        const int lu  = t >> 8;
        const int pos = t & 255;
        const int k   = pos >> 6;
        const int w   = pos & 63;
        const int gu  = u0 + lu;
        float v;
        if (w < 32) v = vecA[idxA[gu * KNB + k] * D + w];
        else        v = vecB[idxB[gu * KNB + k] * D + (w - 32)];
        cat_s[lu][pos] = v;
    }
    __syncthreads();

    const int lu = tid >> 4;    // 0..7
    const int og = tid & 15;    // 0..15 -> 4 output cols each
    const float4* W4 = reinterpret_cast<const float4*>(W);
    float4 acc = make_float4(0.f, 0.f, 0.f, 0.f);
#pragma unroll 8
    for (int i = 0; i < IN_DIM; i++) {
        const float c  = cat_s[lu][i];
        const float4 w4 = W4[i * 16 + og];
        acc.x += c * w4.x; acc.y += c * w4.y;
        acc.z += c * w4.z; acc.w += c * w4.w;
    }
    float* out = side ? g_Vi : g_Vu;
    reinterpret_cast<float4*>(out)[(u0 + lu) * 16 + og] = acc;
}

// ---------------------------------------------------------------------------
// Phase 2: fused flash attention (fp32), O = softmax(Q Q^T / sqrt(D) + 1) @ V'
// followed by ReLU.  Block: 256 threads = 16x16, each thread 4x4 S-subtile
// and 4x4 O-subtile.  BM=BN=64.  K tile and V tile share one smem buffer.
// ---------------------------------------------------------------------------
__global__ __launch_bounds__(256) void flash_kernel(
    const float* __restrict__ user_vecs,
    const float* __restrict__ item_vecs,
    float* __restrict__ out)
{
    __shared__ float Qt[D * SQ];           // transposed: Qt[dd][row]
    __shared__ float KVu[BN * SV];         // union: Kt[D][SK] / Vt[BN][SV]
    __shared__ float Pt[BN * SP];          // transposed P: Pt[col][row]

    const int side = blockIdx.y;
    const float* __restrict__ Q = side ? item_vecs : user_vecs;
    const float* __restrict__ V = side ? g_Vi : g_Vu;
    float* __restrict__ O = out + side * (NQ * DV);

    const int tid = threadIdx.x;
    const int ty = tid >> 4;    // 0..15 -> rows ty*4..+3
    const int tx = tid & 15;    // 0..15 -> cols tx*4..+3
    const int bm0 = blockIdx.x * BM;

    // Load Q tile transposed (once)
    for (int t = tid; t < BM * D; t += 256) {
        const int row = t >> 5, dd = t & 31;
        Qt[dd * SQ + row] = Q[(bm0 + row) * D + dd];
    }

    float m[4], l[4], acc[4][4];
#pragma unroll
    for (int r = 0; r < 4; r++) {
        m[r] = -1e30f; l[r] = 0.f;
#pragma unroll
        for (int c = 0; c < 4; c++) acc[r][c] = 0.f;
    }

    const float scale = 0.17677669529663687f;   // 1/sqrt(32)

    for (int j0 = 0; j0 < NQ; j0 += BN) {
        __syncthreads();   // previous Vt reads done (also orders Qt load, iter 0)
        // --- load K tile transposed into union buffer ---
        for (int t = tid; t < BN * D; t += 256) {
            const int row = t >> 5, dd = t & 31;
            KVu[dd * SK + row] = Q[(j0 + row) * D + dd];
        }
        __syncthreads();

        // --- S = Q K^T ---
        float s[4][4];
#pragma unroll
        for (int r = 0; r < 4; r++)
#pragma unroll
            for (int c = 0; c < 4; c++) s[r][c] = 0.f;

#pragma unroll 8
        for (int dd = 0; dd < D; dd++) {
            const float4 q4 = *reinterpret_cast<const float4*>(&Qt[dd * SQ + ty * 4]);
            const float4 k4 = *reinterpret_cast<const float4*>(&KVu[dd * SK + tx * 4]);
            s[0][0] += q4.x * k4.x; s[0][1] += q4.x * k4.y; s[0][2] += q4.x * k4.z; s[0][3] += q4.x * k4.w;
            s[1][0] += q4.y * k4.x; s[1][1] += q4.y * k4.y; s[1][2] += q4.y * k4.z; s[1][3] += q4.y * k4.w;
            s[2][0] += q4.z * k4.x; s[2][1] += q4.z * k4.y; s[2][2] += q4.z * k4.z; s[2][3] += q4.z * k4.w;
            s[3][0] += q4.w * k4.x; s[3][1] += q4.w * k4.y; s[3][2] += q4.w * k4.z; s[3][3] += q4.w * k4.w;
        }

        // --- online softmax update (row state replicated across 16 tx lanes) ---
        float p[4][4], corr[4];
#pragma unroll
        for (int r = 0; r < 4; r++) {
            float tmax = -1e30f;
#pragma unroll
            for (int c = 0; c < 4; c++) {
                s[r][c] = s[r][c] * scale + 1.0f;
                tmax = fmaxf(tmax, s[r][c]);
            }
#pragma unroll
            for (int o = 8; o >= 1; o >>= 1)
                tmax = fmaxf(tmax, __shfl_xor_sync(0xffffffffu, tmax, o));
            const float mn = fmaxf(m[r], tmax);
            corr[r] = __expf(m[r] - mn);
            float tsum = 0.f;
#pragma unroll
            for (int c = 0; c < 4; c++) {
                p[r][c] = __expf(s[r][c] - mn);
                tsum += p[r][c];
            }
#pragma unroll
            for (int o = 8; o >= 1; o >>= 1)
                tsum += __shfl_xor_sync(0xffffffffu, tsum, o);
            l[r] = l[r] * corr[r] + tsum;
            m[r] = mn;
        }

        // --- write P transposed: Pt[col][row] ---
#pragma unroll
        for (int cc = 0; cc < 4; cc++) {
            const float4 pv = make_float4(p[0][cc], p[1][cc], p[2][cc], p[3][cc]);
            *reinterpret_cast<float4*>(&Pt[(tx * 4 + cc) * SP + ty * 4]) = pv;
        }
        __syncthreads();   // Pt complete; Kt no longer needed

        // --- load V tile into union buffer (overwrites K tile) ---
        for (int t = tid * 4; t < BN * DV; t += 1024) {
            const int row = t >> 6, col = t & 63;
            *reinterpret_cast<float4*>(&KVu[row * SV + col]) =
                *reinterpret_cast<const float4*>(&V[(j0 + row) * DV + col]);
        }
        __syncthreads();

        // --- rescale O, accumulate P @ V ---
#pragma unroll
        for (int r = 0; r < 4; r++) {
            const float cr = corr[r];
#pragma unroll
            for (int c = 0; c < 4; c++) acc[r][c] *= cr;
        }
#pragma unroll 4
        for (int j = 0; j < BN; j++) {
            const float4 p4 = *reinterpret_cast<const float4*>(&Pt[j * SP + ty * 4]);
            const float4 v4 = *reinterpret_cast<const float4*>(&KVu[j * SV + tx * 4]);
            acc[0][0] += p4.x * v4.x; acc[0][1] += p4.x * v4.y; acc[0][2] += p4.x * v4.z; acc[0][3] += p4.x * v4.w;
            acc[1][0] += p4.y * v4.x; acc[1][1] += p4.y * v4.y; acc[1][2] += p4.y * v4.z; acc[1][3] += p4.y * v4.w;
            acc[2][0] += p4.z * v4.x; acc[2][1] += p4.z * v4.y; acc[2][2] += p4.z * v4.z; acc[2][3] += p4.z * v4.w;
            acc[3][0] += p4.w * v4.x; acc[3][1] += p4.w * v4.y; acc[3][2] += p4.w * v4.z; acc[3][3] += p4.w * v4.w;
        }
    }

    // --- epilogue: normalize, ReLU, store ---
#pragma unroll
    for (int r = 0; r < 4; r++) {
        const float inv = 1.f / l[r];
        const int row = bm0 + ty * 4 + r;
        const float4 o4 = make_float4(
            fmaxf(acc[r][0] * inv, 0.f),
            fmaxf(acc[r][1] * inv, 0.f),
            fmaxf(acc[r][2] * inv, 0.f),
            fmaxf(acc[r][3] * inv, 0.f));
        *reinterpret_cast<float4*>(&O[row * DV + tx * 4]) = o4;
    }
}

// ---------------------------------------------------------------------------
// Launch
// ---------------------------------------------------------------------------
extern "C" void kernel_launch(void* const* d_in, const int* in_sizes, int n_in,
                              void* d_out, int out_size)
{
    (void)in_sizes; (void)n_in; (void)out_size;
    const float* review = (const float*)d_in[0];
    const float* user   = (const float*)d_in[1];
    const float* item   = (const float*)d_in[2];
    const int*   adj_ur = (const int*)d_in[3];
    const int*   adj_ri = (const int*)d_in[4];
    const int*   adj_ir = (const int*)d_in[5];
    const int*   adj_ru = (const int*)d_in[6];
    const float* Wu     = (const float*)d_in[7];
    const float* Wi     = (const float*)d_in[8];
    float* out = (float*)d_out;

    // Phase 1: fold gather+concat+W into V' per side
    build_v_kernel<<<NQ / 8, 128>>>(review, adj_ur, item, adj_ri, Wu, 0);
    build_v_kernel<<<NQ / 8, 128>>>(review, adj_ir, user, adj_ru, Wi, 1);

    // Phase 2: fused attention for both sides
    dim3 grid(NQ / BM, 2);
    flash_kernel<<<grid, 256>>>(user, item, out);
}